// round 16
// baseline (speedup 1.0000x reference)
#include <cuda_runtime.h>
#include <cuda_fp16.h>
#include <math.h>

// Problem constants
#define B_  2
#define L_  2048
#define D_  1024
#define H_  16
#define DH_ 64
#define NT  (B_*L_)          // 4096 tokens
#define ND  (B_*H_*L_*DH_)   // 4M elements per Q/K/V

typedef unsigned int uint;

// softmax scale folded into Q: 0.125 * log2(e)
#define QSCALE 0.18033688011112042f

// Scratch. g_v is [B,H,DH,L] (transposed, plain layout).
__device__ __half g_xh[NT * D_];
__device__ __half g_wih[3 * D_ * D_];
__device__ __half g_woh[D_ * D_];
__device__ __half g_q[ND];
__device__ __half g_k[ND];
__device__ __half g_v[ND];
__device__ __half g_ctx[NT * D_];
__device__ float  g_y[NT * D_];

// ---------------------------------------------------------------------------
// helpers
// ---------------------------------------------------------------------------
__device__ __forceinline__ void mma_f16(
    float& c0, float& c1, float& c2, float& c3,
    uint a0, uint a1, uint a2, uint a3, uint b0, uint b1)
{
    asm volatile(
        "mma.sync.aligned.m16n8k16.row.col.f32.f16.f16.f32 "
        "{%0,%1,%2,%3}, {%4,%5,%6,%7}, {%8,%9}, {%0,%1,%2,%3};"
        : "+f"(c0), "+f"(c1), "+f"(c2), "+f"(c3)
        : "r"(a0), "r"(a1), "r"(a2), "r"(a3), "r"(b0), "r"(b1));
}

// ldmatrix x4: lane l supplies row (l&15), k-half (l>>4).
// For A [m][k] rows: regs = {a0,a1,a2,a3} of one m16k16 fragment.
// For B [n][k] rows (row0 spanning 16 n): regs = {b0(nf), b0(nf+1), b1(nf), b1(nf+1)}.
__device__ __forceinline__ void ldsm4(
    uint& r0, uint& r1, uint& r2, uint& r3, uint addr)
{
    asm volatile(
        "ldmatrix.sync.aligned.m8n8.x4.shared.b16 {%0,%1,%2,%3}, [%4];"
        : "=r"(r0), "=r"(r1), "=r"(r2), "=r"(r3) : "r"(addr));
}

__device__ __forceinline__ uint pack2(float lo, float hi) {
    __half2 h = __floats2half2_rn(lo, hi);
    return *reinterpret_cast<uint*>(&h);
}

__device__ __forceinline__ uint smem_u32(const void* p) {
    uint a;
    asm("{ .reg .u64 t; cvta.to.shared.u64 t, %1; cvt.u32.u64 %0, t; }"
        : "=r"(a) : "l"(p));
    return a;
}

__device__ __forceinline__ void cpa16(void* sdst, const void* gsrc) {
    uint d = smem_u32(sdst);
    asm volatile("cp.async.cg.shared.global [%0], [%1], 16;"
                 :: "r"(d), "l"(gsrc) : "memory");
}
#define CPA_COMMIT() asm volatile("cp.async.commit_group;" ::: "memory")
#define CPA_WAIT1()  asm volatile("cp.async.wait_group 1;" ::: "memory")
#define CPA_WAIT0()  asm volatile("cp.async.wait_group 0;" ::: "memory")

// ---------------------------------------------------------------------------
// Prep: one-time fp32 -> fp16 of x, W_in, W_out
// ---------------------------------------------------------------------------
#define NQ_X   (NT * D_ / 4)        // 1048576
#define NQ_WI  (3 * D_ * D_ / 4)    // 786432
#define NQ_WO  (D_ * D_ / 4)        // 262144
__global__ __launch_bounds__(256) void prep_kernel(
    const float* __restrict__ x,
    const float* __restrict__ wi,
    const float* __restrict__ wo)
{
    int q = blockIdx.x * 256 + threadIdx.x;
    const float* src; __half* dst; int off;
    if (q < NQ_X)              { src = x;  dst = g_xh;  off = q; }
    else if (q < NQ_X + NQ_WI) { src = wi; dst = g_wih; off = q - NQ_X; }
    else                       { src = wo; dst = g_woh; off = q - NQ_X - NQ_WI; }
    float4 v = ((const float4*)src)[off];
    uint2 u;
    u.x = pack2(v.x, v.y);
    u.y = pack2(v.z, v.w);
    ((uint2*)dst)[off] = u;
}

// ---------------------------------------------------------------------------
// GEMM mainloop: acc[128x128] += A[bm*128.., K=1024] @ W[bn*128..]^T  (fp16)
// 128 threads, 4 warps (2m x 2n), warp tile 64x64. cp.async double-buffered,
// k-stage 64 halves, pitch 72 halves (144B: LDSM rows hit distinct banks).
// Fragments via ldmatrix.x4: 8 LDSM per k-step vs 16 LDS.64. 3 CTAs/SM.
// ---------------------------------------------------------------------------
#define GP 72   // gemm smem pitch (halves)

__device__ __forceinline__ void gemm_copy_stage(
    __half* As, __half* Bs, const __half* Ab, const __half* Wb, int k0)
{
    const int tid = threadIdx.x;
#pragma unroll
    for (int i = 0; i < 8; i++) {
        int cidx = tid + i * 128;           // 0..1023
        int row = cidx >> 3, kc = cidx & 7; // 8 x 16B chunks per 64-half row
        cpa16(As + row * GP + kc * 8, Ab + (size_t)row * 1024 + k0 + kc * 8);
        cpa16(Bs + row * GP + kc * 8, Wb + (size_t)row * 1024 + k0 + kc * 8);
    }
}

__device__ __forceinline__ void gemm_mainloop(
    __half* sA, __half* sB, const __half* Ab, const __half* Wb, float acc[4][8][4])
{
    const int tid = threadIdx.x;
    const int lane = tid & 31, wid = tid >> 5;
    const int wm = (wid & 1) * 64, wn = (wid >> 1) * 64;

    // per-lane ldmatrix offset (bytes): row = lane&15, k-half = lane>>4
    const uint loff = (((lane & 15) * GP) + ((lane >> 4) * 8)) * 2;
    const uint sAb = smem_u32(sA), sBb = smem_u32(sB);

#pragma unroll
    for (int mf = 0; mf < 4; mf++)
#pragma unroll
        for (int nf = 0; nf < 8; nf++)
#pragma unroll
            for (int r = 0; r < 4; r++) acc[mf][nf][r] = 0.f;

    gemm_copy_stage(sA, sB, Ab, Wb, 0);
    CPA_COMMIT();

    for (int it = 0; it < 16; it++) {
        const int s = it & 1;
        if (it + 1 < 16) {
            gemm_copy_stage(sA + ((it + 1) & 1) * (128 * GP),
                            sB + ((it + 1) & 1) * (128 * GP),
                            Ab, Wb, (it + 1) * 64);
            CPA_COMMIT();
            CPA_WAIT1();
        } else {
            CPA_WAIT0();
        }
        __syncthreads();
        const uint Abase = sAb + s * (128 * GP * 2) + loff;
        const uint Bbase = sBb + s * (128 * GP * 2) + loff;
#pragma unroll
        for (int ks = 0; ks < 4; ks++) {
            uint a[4][4], b[8][2];
#pragma unroll
            for (int mf = 0; mf < 4; mf++)
                ldsm4(a[mf][0], a[mf][1], a[mf][2], a[mf][3],
                      Abase + ((wm + mf * 16) * GP + ks * 16) * 2);
#pragma unroll
            for (int p = 0; p < 4; p++)
                ldsm4(b[2 * p][0], b[2 * p + 1][0], b[2 * p][1], b[2 * p + 1][1],
                      Bbase + ((wn + p * 16) * GP + ks * 16) * 2);
#pragma unroll
            for (int mf = 0; mf < 4; mf++)
#pragma unroll
                for (int nf = 0; nf < 8; nf++)
                    mma_f16(acc[mf][nf][0], acc[mf][nf][1], acc[mf][nf][2], acc[mf][nf][3],
                            a[mf][0], a[mf][1], a[mf][2], a[mf][3],
                            b[nf][0], b[nf][1]);
        }
        __syncthreads();
    }
}

// ---------------------------------------------------------------------------
// GEMM 1: qkv = x @ W_in^T + b_in; Q (pre-scaled by QSCALE) / K -> [B,H,L,DH],
// V -> [B,H,DH,L] (plain transpose). grid (24, 32), 128 threads, 3 CTAs/SM.
// ---------------------------------------------------------------------------
__global__ __launch_bounds__(128, 3) void qkv_gemm(
    const float* __restrict__ bias)
{
    extern __shared__ __half smem[];
    __half* sA = smem;
    __half* sB = smem + 2 * 128 * GP;
    const int bn = blockIdx.x, bm = blockIdx.y;

    float acc[4][8][4];
    gemm_mainloop(sA, sB, g_xh + (size_t)bm * 128 * 1024,
                  g_wih + (size_t)bn * 128 * 1024, acc);

    const int tid = threadIdx.x;
    const int lane = tid & 31, wid = tid >> 5;
    const int wm = (wid & 1) * 64, wn = (wid >> 1) * 64;
    const int g = lane >> 2, c = lane & 3;
    const int part = (bn * 128) >> 10;       // uniform per CTA: 0=Q 1=K 2=V

#pragma unroll
    for (int mf = 0; mf < 4; mf++) {
#pragma unroll
        for (int rr = 0; rr < 2; rr++) {
            int ri = bm * 128 + wm + mf * 16 + g + rr * 8;
            int bb = ri >> 11, l = ri & 2047;
#pragma unroll
            for (int nf = 0; nf < 8; nf++) {
                int n = bn * 128 + wn + nf * 8 + 2 * c;
                float vx = acc[mf][nf][rr * 2 + 0] + bias[n];
                float vy = acc[mf][nf][rr * 2 + 1] + bias[n + 1];
                int hd = n & 1023;
                int h = hd >> 6, dh = hd & 63;
                if (part == 2) {
                    // V transposed [B,H,DH,L]
                    size_t base = ((size_t)(bb * H_ + h) * DH_ + dh) * L_ + l;
                    g_v[base]      = __float2half_rn(vx);
                    g_v[base + L_] = __float2half_rn(vy);
                } else {
                    if (part == 0) { vx *= QSCALE; vy *= QSCALE; }
                    size_t dst = ((size_t)(bb * H_ + h) * L_ + l) * DH_ + dh;
                    __half2 hv = __floats2half2_rn(vx, vy);
                    *(__half2*)((part == 0 ? g_q : g_k) + dst) = hv;
                }
            }
        }
    }
}

// ---------------------------------------------------------------------------
// GEMM 2: y = x + ctx @ W_out^T + b_out ; grid (8, 32), 128 threads
// ---------------------------------------------------------------------------
__global__ __launch_bounds__(128, 3) void out_gemm(
    const float* __restrict__ X,
    const float* __restrict__ bias)
{
    extern __shared__ __half smem[];
    __half* sA = smem;
    __half* sB = smem + 2 * 128 * GP;
    const int bn = blockIdx.x, bm = blockIdx.y;

    float acc[4][8][4];
    gemm_mainloop(sA, sB, g_ctx + (size_t)bm * 128 * 1024,
                  g_woh + (size_t)bn * 128 * 1024, acc);

    const int tid = threadIdx.x;
    const int lane = tid & 31, wid = tid >> 5;
    const int wm = (wid & 1) * 64, wn = (wid >> 1) * 64;
    const int g = lane >> 2, c = lane & 3;

#pragma unroll
    for (int mf = 0; mf < 4; mf++) {
#pragma unroll
        for (int rr = 0; rr < 2; rr++) {
            int ri = bm * 128 + wm + mf * 16 + g + rr * 8;
#pragma unroll
            for (int nf = 0; nf < 8; nf++) {
                int n = bn * 128 + wn + nf * 8 + 2 * c;
                float2 v;
                v.x = acc[mf][nf][rr * 2 + 0] + bias[n]     + X[(size_t)ri * 1024 + n];
                v.y = acc[mf][nf][rr * 2 + 1] + bias[n + 1] + X[(size_t)ri * 1024 + n + 1];
                *(float2*)(g_y + (size_t)ri * 1024 + n) = v;
            }
        }
    }
}

// ---------------------------------------------------------------------------
// Flash attention, fp16 mma.sync + ldmatrix fragments. 256 threads,
// 8 warps x 16 q-rows, 2 CTAs/SM target. Q pre-scaled by 0.125*log2e;
// softmax via exp2. cp.async double-buffered K [key][dh] and V^T [dh][key].
// S's C-fragment feeds PV's A-fragment in registers (standard FA2 identity).
// Softmax is invariant to the per-batch "vol" constant -> market_info dropped.
// ---------------------------------------------------------------------------
#define AP 72   // attn smem pitch (halves)
__global__ __launch_bounds__(256, 2) void attn_f16()
{
    extern __shared__ __half sm[];
    __half* Qs = sm;                      // 128 x AP
    __half* Ks = Qs + 128 * AP;           // 2 x 64 x AP  ([key][dh])
    __half* Vs = Ks + 2 * 64 * AP;        // 2 x 64 x AP  ([dh][key])

    const int bh = blockIdx.y;            // 0..31
    const int bb = bh >> 4, h = bh & 15;
    const int q0 = blockIdx.x * 128;
    const int tid = threadIdx.x;
    const int lane = tid & 31, w = tid >> 5;   // w: 0..7
    const int g = lane >> 2, c = lane & 3;
    const uint loff = (((lane & 15) * AP) + ((lane >> 4) * 8)) * 2;
    const uint Qb = smem_u32(Qs), Kb = smem_u32(Ks), Vb = smem_u32(Vs);

    const __half* Qg  = g_q + ((size_t)bh * L_ + q0) * DH_;
    const __half* Kg  = g_k + (size_t)bh * L_ * DH_;
    const __half* VgT = g_v + (size_t)bh * DH_ * L_;   // [DH][L]

    // Q tile (128 x 64 halves)
#pragma unroll
    for (int i = 0; i < 4; i++) {
        int cidx = tid + i * 256;         // 0..1023
        int r = cidx >> 3, kc = cidx & 7;
        cpa16(Qs + r * AP + kc * 8, Qg + (size_t)r * 64 + kc * 8);
    }
    // K/V tile 0 -> buffer 0
#pragma unroll
    for (int i = 0; i < 2; i++) {
        int cidx = tid + i * 256;         // 0..511
        int r = cidx >> 3, kc = cidx & 7;
        cpa16(Ks + r * AP + kc * 8, Kg + (size_t)r * 64 + kc * 8);
        cpa16(Vs + r * AP + kc * 8, VgT + (size_t)r * L_ + kc * 8);
    }
    CPA_COMMIT();
    // K/V tile 1 -> buffer 1
#pragma unroll
    for (int i = 0; i < 2; i++) {
        int cidx = tid + i * 256;
        int r = cidx >> 3, kc = cidx & 7;
        cpa16(Ks + 64 * AP + r * AP + kc * 8, Kg + (size_t)(64 + r) * 64 + kc * 8);
        cpa16(Vs + 64 * AP + r * AP + kc * 8, VgT + (size_t)r * L_ + 64 + kc * 8);
    }
    CPA_COMMIT();
    CPA_WAIT1();                          // Q + tile 0 resident
    __syncthreads();

    // Hoist Q fragments (16 rows for this warp) via ldmatrix
    uint qa[4][4];
#pragma unroll
    for (int ks = 0; ks < 4; ks++)
        ldsm4(qa[ks][0], qa[ks][1], qa[ks][2], qa[ks][3],
              Qb + ((w * 16) * AP + ks * 16) * 2 + loff);

    float m0 = -1e30f, m1 = -1e30f, l0 = 0.f, l1 = 0.f;
    float o[8][4];
#pragma unroll
    for (int nf = 0; nf < 8; nf++)
#pragma unroll
        for (int r = 0; r < 4; r++) o[nf][r] = 0.f;

    const int NTILE = L_ / 64;            // 32
    for (int kt = 0; kt < NTILE; kt++) {
        const int s = kt & 1;
        const uint Kub = Kb + s * (64 * AP * 2) + loff;
        const uint Vub = Vb + s * (64 * AP * 2) + loff;

        // --- S = Q @ K^T (warp tile 16 x 64), B-frags via ldmatrix ---
        float sc[8][4];
#pragma unroll
        for (int nf = 0; nf < 8; nf++)
#pragma unroll
            for (int r = 0; r < 4; r++) sc[nf][r] = 0.f;
#pragma unroll
        for (int ks = 0; ks < 4; ks++) {
#pragma unroll
            for (int p = 0; p < 4; p++) {
                uint b00, b01, b10, b11;
                ldsm4(b00, b01, b10, b11,
                      Kub + ((p * 16) * AP + ks * 16) * 2);
                mma_f16(sc[2 * p][0], sc[2 * p][1], sc[2 * p][2], sc[2 * p][3],
                        qa[ks][0], qa[ks][1], qa[ks][2], qa[ks][3], b00, b10);
                mma_f16(sc[2 * p + 1][0], sc[2 * p + 1][1], sc[2 * p + 1][2], sc[2 * p + 1][3],
                        qa[ks][0], qa[ks][1], qa[ks][2], qa[ks][3], b01, b11);
            }
        }

        // --- online softmax, exp2 domain (rows g / g+8) ---
        float mx0 = -1e30f, mx1 = -1e30f;
#pragma unroll
        for (int nf = 0; nf < 8; nf++) {
            mx0 = fmaxf(mx0, fmaxf(sc[nf][0], sc[nf][1]));
            mx1 = fmaxf(mx1, fmaxf(sc[nf][2], sc[nf][3]));
        }
        mx0 = fmaxf(mx0, __shfl_xor_sync(0xffffffffu, mx0, 1));
        mx0 = fmaxf(mx0, __shfl_xor_sync(0xffffffffu, mx0, 2));
        mx1 = fmaxf(mx1, __shfl_xor_sync(0xffffffffu, mx1, 1));
        mx1 = fmaxf(mx1, __shfl_xor_sync(0xffffffffu, mx1, 2));
        float mn0 = fmaxf(m0, mx0), mn1 = fmaxf(m1, mx1);
        float al0 = exp2f(m0 - mn0), al1 = exp2f(m1 - mn1);
        float ls0 = 0.f, ls1 = 0.f;
#pragma unroll
        for (int nf = 0; nf < 8; nf++) {
            sc[nf][0] = exp2f(sc[nf][0] - mn0);
            sc[nf][1] = exp2f(sc[nf][1] - mn0);
            sc[nf][2] = exp2f(sc[nf][2] - mn1);
            sc[nf][3] = exp2f(sc[nf][3] - mn1);
            ls0 += sc[nf][0] + sc[nf][1];
            ls1 += sc[nf][2] + sc[nf][3];
        }
        ls0 += __shfl_xor_sync(0xffffffffu, ls0, 1);
        ls0 += __shfl_xor_sync(0xffffffffu, ls0, 2);
        ls1 += __shfl_xor_sync(0xffffffffu, ls1, 1);
        ls1 += __shfl_xor_sync(0xffffffffu, ls1, 2);
        l0 = l0 * al0 + ls0; m0 = mn0;
        l1 = l1 * al1 + ls1; m1 = mn1;
#pragma unroll
        for (int nf = 0; nf < 8; nf++) {
            o[nf][0] *= al0; o[nf][1] *= al0;
            o[nf][2] *= al1; o[nf][3] *= al1;
        }

        // --- O += P @ V: pack S C-frag into A-frag; V b-frags via ldmatrix ---
#pragma unroll
        for (int t = 0; t < 4; t++) {
            uint a0 = pack2(sc[2 * t][0],     sc[2 * t][1]);
            uint a1 = pack2(sc[2 * t][2],     sc[2 * t][3]);
            uint a2 = pack2(sc[2 * t + 1][0], sc[2 * t + 1][1]);
            uint a3 = pack2(sc[2 * t + 1][2], sc[2 * t + 1][3]);
#pragma unroll
            for (int p = 0; p < 4; p++) {
                uint b00, b01, b10, b11;
                ldsm4(b00, b01, b10, b11,
                      Vub + ((p * 16) * AP + t * 16) * 2);
                mma_f16(o[2 * p][0], o[2 * p][1], o[2 * p][2], o[2 * p][3],
                        a0, a1, a2, a3, b00, b10);
                mma_f16(o[2 * p + 1][0], o[2 * p + 1][1], o[2 * p + 1][2], o[2 * p + 1][3],
                        a0, a1, a2, a3, b01, b11);
            }
        }

        // prefetch kt+2 into this buffer, wait for kt+1
        __syncthreads();                   // all warps done reading buffer s
        if (kt + 2 < NTILE) {
            const __half* Kt  = Kg  + (size_t)(kt + 2) * 64 * 64;
            const __half* Vtg = VgT + (size_t)(kt + 2) * 64;
            __half* Kd = Ks + s * 64 * AP;
            __half* Vd = Vs + s * 64 * AP;
#pragma unroll
            for (int i = 0; i < 2; i++) {
                int cidx = tid + i * 256;
                int r = cidx >> 3, kc = cidx & 7;
                cpa16(Kd + r * AP + kc * 8, Kt + (size_t)r * 64 + kc * 8);
                cpa16(Vd + r * AP + kc * 8, Vtg + (size_t)r * L_ + kc * 8);
            }
            CPA_COMMIT();
            CPA_WAIT1();
        } else {
            CPA_WAIT0();
        }
        __syncthreads();                   // kt+1 data visible to all warps
    }

    // Epilogue: write ctx fp16, layout [B,L,H*DH]
    float inv0 = 1.0f / l0, inv1 = 1.0f / l1;
    int r0 = q0 + w * 16 + g;
    int r1 = r0 + 8;
#pragma unroll
    for (int nf = 0; nf < 8; nf++) {
        int col = h * 64 + nf * 8 + 2 * c;
        __half2 u0 = __floats2half2_rn(o[nf][0] * inv0, o[nf][1] * inv0);
        __half2 u1 = __floats2half2_rn(o[nf][2] * inv1, o[nf][3] * inv1);
        *(__half2*)(g_ctx + (size_t)(bb * L_ + r0) * 1024 + col) = u0;
        *(__half2*)(g_ctx + (size_t)(bb * L_ + r1) * 1024 + col) = u1;
    }
}

// ---------------------------------------------------------------------------
// LayerNorm over last dim (1024), one block per token row
// ---------------------------------------------------------------------------
__global__ __launch_bounds__(256) void ln_kernel(
    const float* __restrict__ gamma,
    const float* __restrict__ beta,
    float* __restrict__ out)
{
    const int row = blockIdx.x;
    const float* yr = g_y + (size_t)row * 1024;
    const int tid = threadIdx.x;

    float s = 0.f, sq = 0.f;
#pragma unroll
    for (int i = tid; i < 1024; i += 256) {
        float v = yr[i];
        s += v;
        sq += v * v;
    }
#pragma unroll
    for (int off = 16; off > 0; off >>= 1) {
        s  += __shfl_xor_sync(0xffffffffu, s, off);
        sq += __shfl_xor_sync(0xffffffffu, sq, off);
    }
    __shared__ float ws[8], wq[8];
    __shared__ float mu_s, rstd_s;
    int w = tid >> 5;
    if ((tid & 31) == 0) { ws[w] = s; wq[w] = sq; }
    __syncthreads();
    if (tid == 0) {
        float S = 0.f, Q = 0.f;
#pragma unroll
        for (int i = 0; i < 8; i++) { S += ws[i]; Q += wq[i]; }
        float mu = S * (1.0f / 1024.0f);
        float var = Q * (1.0f / 1024.0f) - mu * mu;
        mu_s = mu;
        rstd_s = rsqrtf(var + 1e-5f);
    }
    __syncthreads();
    float mu = mu_s, rstd = rstd_s;
#pragma unroll
    for (int i = tid; i < 1024; i += 256) {
        out[(size_t)row * 1024 + i] = (yr[i] - mu) * rstd * gamma[i] + beta[i];
    }
}

// ---------------------------------------------------------------------------
extern "C" void kernel_launch(void* const* d_in, const int* in_sizes, int n_in,
                              void* d_out, int out_size)
{
    const float* x      = (const float*)d_in[0];
    // d_in[1] = market_info: softmax-invariant constant, unused
    const float* w_in   = (const float*)d_in[2];
    const float* b_in   = (const float*)d_in[3];
    const float* w_out  = (const float*)d_in[4];
    const float* b_out  = (const float*)d_in[5];
    const float* gamma  = (const float*)d_in[6];
    const float* beta   = (const float*)d_in[7];
    float* out = (float*)d_out;

    // fp32 -> fp16 prep (x, W_in, W_out)
    prep_kernel<<<(NQ_X + NQ_WI + NQ_WO) / 256, 256>>>(x, w_in, w_out);

    // GEMM smem: 2 buffers x (A + B) x 128 x 72 halves = 73728 B -> 3 CTAs/SM
    const int gemm_smem = 4 * 128 * GP * (int)sizeof(__half);
    cudaFuncSetAttribute(qkv_gemm, cudaFuncAttributeMaxDynamicSharedMemorySize, gemm_smem);
    cudaFuncSetAttribute(out_gemm, cudaFuncAttributeMaxDynamicSharedMemorySize, gemm_smem);

    // QKV projection
    qkv_gemm<<<dim3(24, 32), 128, gemm_smem>>>(b_in);

    // Attention: smem = (128 + 2*64 + 2*64) * 72 halves = 55296 B -> 2 CTAs/SM
    const int attn_smem = 384 * AP * (int)sizeof(__half);
    cudaFuncSetAttribute(attn_f16, cudaFuncAttributeMaxDynamicSharedMemorySize,
                         attn_smem);
    attn_f16<<<dim3(L_ / 128, B_ * H_), 256, attn_smem>>>();

    // Output projection + residual
    out_gemm<<<dim3(8, 32), 128, gemm_smem>>>(x, b_out);

    // LayerNorm
    ln_kernel<<<NT, 256>>>(gamma, beta, out);
}

// round 17
// speedup vs baseline: 1.1351x; 1.1351x over previous
#include <cuda_runtime.h>
#include <cuda_fp16.h>
#include <math.h>

// Problem constants
#define B_  2
#define L_  2048
#define D_  1024
#define H_  16
#define DH_ 64
#define NT  (B_*L_)          // 4096 tokens
#define ND  (B_*H_*L_*DH_)   // 4M elements per Q/K/V

typedef unsigned int uint;

// softmax scale folded into Q: 0.125 * log2(e)
#define QSCALE 0.18033688011112042f

// Scratch. g_v is [B,H,DH,L] (transposed), keys permuted within 16-blocks.
__device__ __half g_xh[NT * D_];
__device__ __half g_wih[3 * D_ * D_];
__device__ __half g_woh[D_ * D_];
__device__ __half g_q[ND];
__device__ __half g_k[ND];
__device__ __half g_v[ND];
__device__ __half g_ctx[NT * D_];
__device__ float  g_y[NT * D_];

// ---------------------------------------------------------------------------
// helpers
// ---------------------------------------------------------------------------
__device__ __forceinline__ void mma_f16(
    float& c0, float& c1, float& c2, float& c3,
    uint a0, uint a1, uint a2, uint a3, uint b0, uint b1)
{
    asm volatile(
        "mma.sync.aligned.m16n8k16.row.col.f32.f16.f16.f32 "
        "{%0,%1,%2,%3}, {%4,%5,%6,%7}, {%8,%9}, {%0,%1,%2,%3};"
        : "+f"(c0), "+f"(c1), "+f"(c2), "+f"(c3)
        : "r"(a0), "r"(a1), "r"(a2), "r"(a3), "r"(b0), "r"(b1));
}

__device__ __forceinline__ uint pack2(float lo, float hi) {
    __half2 h = __floats2half2_rn(lo, hi);
    return *reinterpret_cast<uint*>(&h);
}

__device__ __forceinline__ uint smem_u32(const void* p) {
    uint a;
    asm("{ .reg .u64 t; cvta.to.shared.u64 t, %1; cvt.u32.u64 %0, t; }"
        : "=r"(a) : "l"(p));
    return a;
}

__device__ __forceinline__ void cpa16(void* sdst, const void* gsrc) {
    uint d = smem_u32(sdst);
    asm volatile("cp.async.cg.shared.global [%0], [%1], 16;"
                 :: "r"(d), "l"(gsrc) : "memory");
}
#define CPA_COMMIT() asm volatile("cp.async.commit_group;" ::: "memory")
#define CPA_WAIT1()  asm volatile("cp.async.wait_group 1;" ::: "memory")
#define CPA_WAIT0()  asm volatile("cp.async.wait_group 0;" ::: "memory")

// ---------------------------------------------------------------------------
// Prep: one-time fp32 -> fp16 of x, W_in, W_out
// ---------------------------------------------------------------------------
#define NQ_X   (NT * D_ / 4)        // 1048576
#define NQ_WI  (3 * D_ * D_ / 4)    // 786432
#define NQ_WO  (D_ * D_ / 4)        // 262144
__global__ __launch_bounds__(256) void prep_kernel(
    const float* __restrict__ x,
    const float* __restrict__ wi,
    const float* __restrict__ wo)
{
    int q = blockIdx.x * 256 + threadIdx.x;
    const float* src; __half* dst; int off;
    if (q < NQ_X)              { src = x;  dst = g_xh;  off = q; }
    else if (q < NQ_X + NQ_WI) { src = wi; dst = g_wih; off = q - NQ_X; }
    else                       { src = wo; dst = g_woh; off = q - NQ_X - NQ_WI; }
    float4 v = ((const float4*)src)[off];
    uint2 u;
    u.x = pack2(v.x, v.y);
    u.y = pack2(v.z, v.w);
    ((uint2*)dst)[off] = u;
}

// ---------------------------------------------------------------------------
// GEMM mainloop: acc[128x128] += A[bm*128.., K=1024] @ W[bn*128..]^T  (fp16)
// 128 threads, 4 warps (2m x 2n), warp tile 64x64. cp.async double-buffered,
// k-stage 32 halves (64B rows), pitch 48 halves (96B):
//   - LDS.64 fragment loads: bank = (24g + 2c + 8ks) mod 32, conflict-free
//   - cp.async stores use a row-interleaved lane map (rows {r,r+2}|{r+1,r+3}
//     per 16 lanes) so each 8-lane STS phase covers all 32 banks.
// smem = 49152 B -> 3 CTAs/SM (12 warps). R14-proven fragment scheme.
// ---------------------------------------------------------------------------
#define GP 48   // gemm smem pitch (halves)

__device__ __forceinline__ void gemm_copy_stage(
    __half* As, __half* Bs, const __half* Ab, const __half* Wb, int k0)
{
    const int tid = threadIdx.x;
#pragma unroll
    for (int i = 0; i < 4; i++) {
        int cidx = tid + i * 128;           // 0..511 (128 rows x 4 chunks)
        int l16 = cidx & 15;
        int row = ((cidx >> 4) << 2) + 2 * ((l16 >> 2) & 1) + (l16 >> 3);
        int p = l16 & 3;                    // 16B chunk within the 64B row
        cpa16(As + row * GP + p * 8, Ab + (size_t)row * 1024 + k0 + p * 8);
        cpa16(Bs + row * GP + p * 8, Wb + (size_t)row * 1024 + k0 + p * 8);
    }
}

__device__ __forceinline__ void gemm_mainloop(
    __half* sA, __half* sB, const __half* Ab, const __half* Wb, float acc[4][8][4])
{
    const int tid = threadIdx.x;
    const int lane = tid & 31, wid = tid >> 5;
    const int wm = (wid & 1) * 64, wn = (wid >> 1) * 64;
    const int g = lane >> 2, c = lane & 3;

#pragma unroll
    for (int mf = 0; mf < 4; mf++)
#pragma unroll
        for (int nf = 0; nf < 8; nf++)
#pragma unroll
            for (int r = 0; r < 4; r++) acc[mf][nf][r] = 0.f;

    gemm_copy_stage(sA, sB, Ab, Wb, 0);
    CPA_COMMIT();

    for (int it = 0; it < 32; it++) {
        const int s = it & 1;
        if (it + 1 < 32) {
            gemm_copy_stage(sA + ((it + 1) & 1) * (128 * GP),
                            sB + ((it + 1) & 1) * (128 * GP),
                            Ab, Wb, (it + 1) * 32);
            CPA_COMMIT();
            CPA_WAIT1();
        } else {
            CPA_WAIT0();
        }
        __syncthreads();
        const __half* A  = sA + s * (128 * GP);
        const __half* Bt = sB + s * (128 * GP);
#pragma unroll
        for (int ks = 0; ks < 2; ks++) {
            uint a[4][4], b[8][2];
#pragma unroll
            for (int mf = 0; mf < 4; mf++) {
                uint2 t0 = *(const uint2*)(A + (wm + mf * 16 + g) * GP + ks * 16 + 4 * c);
                uint2 t1 = *(const uint2*)(A + (wm + mf * 16 + g + 8) * GP + ks * 16 + 4 * c);
                a[mf][0] = t0.x; a[mf][1] = t1.x;
                a[mf][2] = t0.y; a[mf][3] = t1.y;
            }
#pragma unroll
            for (int nf = 0; nf < 8; nf++) {
                uint2 tb = *(const uint2*)(Bt + (wn + nf * 8 + g) * GP + ks * 16 + 4 * c);
                b[nf][0] = tb.x; b[nf][1] = tb.y;
            }
#pragma unroll
            for (int mf = 0; mf < 4; mf++)
#pragma unroll
                for (int nf = 0; nf < 8; nf++)
                    mma_f16(acc[mf][nf][0], acc[mf][nf][1], acc[mf][nf][2], acc[mf][nf][3],
                            a[mf][0], a[mf][1], a[mf][2], a[mf][3],
                            b[nf][0], b[nf][1]);
        }
        __syncthreads();
    }
}

// ---------------------------------------------------------------------------
// GEMM 1: qkv = x @ W_in^T + b_in; Q (pre-scaled by QSCALE) / K -> [B,H,L,DH],
// V -> [B,H,DH,L] fp16 with keys permuted per 16-block.
// grid (24, 32), 128 threads, 3 CTAs/SM
// ---------------------------------------------------------------------------
__global__ __launch_bounds__(128, 3) void qkv_gemm(
    const float* __restrict__ bias)
{
    extern __shared__ __half smem[];
    __half* sA = smem;
    __half* sB = smem + 2 * 128 * GP;
    const int bn = blockIdx.x, bm = blockIdx.y;

    float acc[4][8][4];
    gemm_mainloop(sA, sB, g_xh + (size_t)bm * 128 * 1024,
                  g_wih + (size_t)bn * 128 * 1024, acc);

    const int tid = threadIdx.x;
    const int lane = tid & 31, wid = tid >> 5;
    const int wm = (wid & 1) * 64, wn = (wid >> 1) * 64;
    const int g = lane >> 2, c = lane & 3;
    const int part = (bn * 128) >> 10;       // uniform per CTA: 0=Q 1=K 2=V

#pragma unroll
    for (int mf = 0; mf < 4; mf++) {
#pragma unroll
        for (int rr = 0; rr < 2; rr++) {
            int ri = bm * 128 + wm + mf * 16 + g + rr * 8;
            int bb = ri >> 11, l = ri & 2047;
#pragma unroll
            for (int nf = 0; nf < 8; nf++) {
                int n = bn * 128 + wn + nf * 8 + 2 * c;
                float vx = acc[mf][nf][rr * 2 + 0] + bias[n];
                float vy = acc[mf][nf][rr * 2 + 1] + bias[n + 1];
                int hd = n & 1023;
                int h = hd >> 6, dh = hd & 63;
                if (part == 2) {
                    // V transposed [B,H,DH,L], key permuted within 16-block
                    int o = l & 15;
                    int pos = (o < 8) ? (((o >> 1) << 2) | (o & 1))
                                      : ((((o - 8) >> 1) << 2) + 2 + (o & 1));
                    int lp = (l & ~15) | pos;
                    size_t base = ((size_t)(bb * H_ + h) * DH_ + dh) * L_ + lp;
                    g_v[base]      = __float2half_rn(vx);
                    g_v[base + L_] = __float2half_rn(vy);
                } else {
                    if (part == 0) { vx *= QSCALE; vy *= QSCALE; }
                    size_t dst = ((size_t)(bb * H_ + h) * L_ + l) * DH_ + dh;
                    __half2 hv = __floats2half2_rn(vx, vy);
                    *(__half2*)((part == 0 ? g_q : g_k) + dst) = hv;
                }
            }
        }
    }
}

// ---------------------------------------------------------------------------
// GEMM 2: y = x + ctx @ W_out^T + b_out ; grid (8, 32), 128 threads, 3 CTAs/SM
// ---------------------------------------------------------------------------
__global__ __launch_bounds__(128, 3) void out_gemm(
    const float* __restrict__ X,
    const float* __restrict__ bias)
{
    extern __shared__ __half smem[];
    __half* sA = smem;
    __half* sB = smem + 2 * 128 * GP;
    const int bn = blockIdx.x, bm = blockIdx.y;

    float acc[4][8][4];
    gemm_mainloop(sA, sB, g_ctx + (size_t)bm * 128 * 1024,
                  g_woh + (size_t)bn * 128 * 1024, acc);

    const int tid = threadIdx.x;
    const int lane = tid & 31, wid = tid >> 5;
    const int wm = (wid & 1) * 64, wn = (wid >> 1) * 64;
    const int g = lane >> 2, c = lane & 3;

#pragma unroll
    for (int mf = 0; mf < 4; mf++) {
#pragma unroll
        for (int rr = 0; rr < 2; rr++) {
            int ri = bm * 128 + wm + mf * 16 + g + rr * 8;
#pragma unroll
            for (int nf = 0; nf < 8; nf++) {
                int n = bn * 128 + wn + nf * 8 + 2 * c;
                float2 v;
                v.x = acc[mf][nf][rr * 2 + 0] + bias[n]     + X[(size_t)ri * 1024 + n];
                v.y = acc[mf][nf][rr * 2 + 1] + bias[n + 1] + X[(size_t)ri * 1024 + n + 1];
                *(float2*)(g_y + (size_t)ri * 1024 + n) = v;
            }
        }
    }
}

// ---------------------------------------------------------------------------
// Flash attention, fp16 mma.sync (R14-proven version). 128 threads, 4 warps;
// each warp owns 32 q-rows (two 16-row halves): K/V b-fragments loaded ONCE
// and shared by both halves' MMAs. cp.async double-buffered K and permuted
// V^T. Q pre-scaled by 0.125*log2e in qkv; softmax via exp2.
// Softmax is invariant to the per-batch "vol" constant -> market_info dropped.
// ---------------------------------------------------------------------------
#define AP 80   // attn smem pitch (halves)
__global__ __launch_bounds__(128) void attn_f16()
{
    extern __shared__ __half sm[];
    __half* Qs = sm;                      // 128 x AP
    __half* Ks = Qs + 128 * AP;           // 2 x 64 x AP  ([key][dh])
    __half* Vs = Ks + 2 * 64 * AP;        // 2 x 64 x AP  ([dh][key-permuted])

    const int bh = blockIdx.y;            // 0..31
    const int bb = bh >> 4, h = bh & 15;
    const int q0 = blockIdx.x * 128;
    const int tid = threadIdx.x;
    const int lane = tid & 31, w = tid >> 5;   // w: 0..3
    const int g = lane >> 2, c = lane & 3;

    const __half* Qg  = g_q + ((size_t)bh * L_ + q0) * DH_;
    const __half* Kg  = g_k + (size_t)bh * L_ * DH_;
    const __half* VgT = g_v + (size_t)bh * DH_ * L_;   // [DH][L]

    // Q tile (128 x 64 halves)
#pragma unroll
    for (int i = 0; i < 8; i++) {
        int cidx = tid + i * 128;         // 0..1023
        int r = cidx >> 3, kc = cidx & 7;
        cpa16(Qs + r * AP + kc * 8, Qg + (size_t)r * 64 + kc * 8);
    }
    // K/V tile 0 -> buffer 0
#pragma unroll
    for (int i = 0; i < 4; i++) {
        int cidx = tid + i * 128;         // 0..511
        int r = cidx >> 3, kc = cidx & 7;
        cpa16(Ks + r * AP + kc * 8, Kg + (size_t)r * 64 + kc * 8);
        cpa16(Vs + r * AP + kc * 8, VgT + (size_t)r * L_ + kc * 8);
    }
    CPA_COMMIT();
    // K/V tile 1 -> buffer 1
#pragma unroll
    for (int i = 0; i < 4; i++) {
        int cidx = tid + i * 128;
        int r = cidx >> 3, kc = cidx & 7;
        cpa16(Ks + 64 * AP + r * AP + kc * 8, Kg + (size_t)(64 + r) * 64 + kc * 8);
        cpa16(Vs + 64 * AP + r * AP + kc * 8, VgT + (size_t)r * L_ + 64 + kc * 8);
    }
    CPA_COMMIT();
    CPA_WAIT1();                          // Q + tile 0 resident
    __syncthreads();

    // Hoist Q fragments for both 16-row halves
    uint qa[2][4][4];
#pragma unroll
    for (int hm = 0; hm < 2; hm++) {
#pragma unroll
        for (int ks = 0; ks < 4; ks++) {
            uint2 t0 = *(const uint2*)(Qs + (w * 32 + hm * 16 + g) * AP + ks * 16 + 4 * c);
            uint2 t1 = *(const uint2*)(Qs + (w * 32 + hm * 16 + g + 8) * AP + ks * 16 + 4 * c);
            qa[hm][ks][0] = t0.x; qa[hm][ks][1] = t1.x;
            qa[hm][ks][2] = t0.y; qa[hm][ks][3] = t1.y;
        }
    }

    float m[4], l[4];
#pragma unroll
    for (int i = 0; i < 4; i++) { m[i] = -1e30f; l[i] = 0.f; }
    float o[2][8][4];
#pragma unroll
    for (int hm = 0; hm < 2; hm++)
#pragma unroll
        for (int nf = 0; nf < 8; nf++)
#pragma unroll
            for (int r = 0; r < 4; r++) o[hm][nf][r] = 0.f;

    const int NTILE = L_ / 64;            // 32
    for (int kt = 0; kt < NTILE; kt++) {
        const int s = kt & 1;
        const __half* Ku = Ks + s * 64 * AP;
        const __half* Vu = Vs + s * 64 * AP;

        // --- S = Q @ K^T: K frag loaded once, feeds both halves ---
        float sc[2][8][4];
#pragma unroll
        for (int hm = 0; hm < 2; hm++)
#pragma unroll
            for (int nf = 0; nf < 8; nf++)
#pragma unroll
                for (int r = 0; r < 4; r++) sc[hm][nf][r] = 0.f;
#pragma unroll
        for (int ks = 0; ks < 4; ks++) {
#pragma unroll
            for (int nf = 0; nf < 8; nf++) {
                uint2 kb = *(const uint2*)(Ku + (nf * 8 + g) * AP + ks * 16 + 4 * c);
                mma_f16(sc[0][nf][0], sc[0][nf][1], sc[0][nf][2], sc[0][nf][3],
                        qa[0][ks][0], qa[0][ks][1], qa[0][ks][2], qa[0][ks][3],
                        kb.x, kb.y);
                mma_f16(sc[1][nf][0], sc[1][nf][1], sc[1][nf][2], sc[1][nf][3],
                        qa[1][ks][0], qa[1][ks][1], qa[1][ks][2], qa[1][ks][3],
                        kb.x, kb.y);
            }
        }

        // --- online softmax per half, exp2 domain (rows g / g+8) ---
#pragma unroll
        for (int hm = 0; hm < 2; hm++) {
            float mx0 = -1e30f, mx1 = -1e30f;
#pragma unroll
            for (int nf = 0; nf < 8; nf++) {
                mx0 = fmaxf(mx0, fmaxf(sc[hm][nf][0], sc[hm][nf][1]));
                mx1 = fmaxf(mx1, fmaxf(sc[hm][nf][2], sc[hm][nf][3]));
            }
            mx0 = fmaxf(mx0, __shfl_xor_sync(0xffffffffu, mx0, 1));
            mx0 = fmaxf(mx0, __shfl_xor_sync(0xffffffffu, mx0, 2));
            mx1 = fmaxf(mx1, __shfl_xor_sync(0xffffffffu, mx1, 1));
            mx1 = fmaxf(mx1, __shfl_xor_sync(0xffffffffu, mx1, 2));
            float mn0 = fmaxf(m[hm * 2], mx0), mn1 = fmaxf(m[hm * 2 + 1], mx1);
            float al0 = exp2f(m[hm * 2] - mn0), al1 = exp2f(m[hm * 2 + 1] - mn1);
            float ls0 = 0.f, ls1 = 0.f;
#pragma unroll
            for (int nf = 0; nf < 8; nf++) {
                sc[hm][nf][0] = exp2f(sc[hm][nf][0] - mn0);
                sc[hm][nf][1] = exp2f(sc[hm][nf][1] - mn0);
                sc[hm][nf][2] = exp2f(sc[hm][nf][2] - mn1);
                sc[hm][nf][3] = exp2f(sc[hm][nf][3] - mn1);
                ls0 += sc[hm][nf][0] + sc[hm][nf][1];
                ls1 += sc[hm][nf][2] + sc[hm][nf][3];
            }
            ls0 += __shfl_xor_sync(0xffffffffu, ls0, 1);
            ls0 += __shfl_xor_sync(0xffffffffu, ls0, 2);
            ls1 += __shfl_xor_sync(0xffffffffu, ls1, 1);
            ls1 += __shfl_xor_sync(0xffffffffu, ls1, 2);
            l[hm * 2]     = l[hm * 2]     * al0 + ls0;  m[hm * 2]     = mn0;
            l[hm * 2 + 1] = l[hm * 2 + 1] * al1 + ls1;  m[hm * 2 + 1] = mn1;
#pragma unroll
            for (int nf = 0; nf < 8; nf++) {
                o[hm][nf][0] *= al0; o[hm][nf][1] *= al0;
                o[hm][nf][2] *= al1; o[hm][nf][3] *= al1;
            }
        }

        // --- O += P @ V: V frag loaded once, feeds both halves ---
#pragma unroll
        for (int t = 0; t < 4; t++) {
            uint a0[2], a1[2], a2[2], a3[2];
#pragma unroll
            for (int hm = 0; hm < 2; hm++) {
                a0[hm] = pack2(sc[hm][2 * t][0],     sc[hm][2 * t][1]);
                a1[hm] = pack2(sc[hm][2 * t][2],     sc[hm][2 * t][3]);
                a2[hm] = pack2(sc[hm][2 * t + 1][0], sc[hm][2 * t + 1][1]);
                a3[hm] = pack2(sc[hm][2 * t + 1][2], sc[hm][2 * t + 1][3]);
            }
#pragma unroll
            for (int nf = 0; nf < 8; nf++) {
                uint2 vb = *(const uint2*)(Vu + (nf * 8 + g) * AP + t * 16 + 4 * c);
                mma_f16(o[0][nf][0], o[0][nf][1], o[0][nf][2], o[0][nf][3],
                        a0[0], a1[0], a2[0], a3[0], vb.x, vb.y);
                mma_f16(o[1][nf][0], o[1][nf][1], o[1][nf][2], o[1][nf][3],
                        a0[1], a1[1], a2[1], a3[1], vb.x, vb.y);
            }
        }

        // prefetch kt+2 into this buffer, wait for kt+1
        __syncthreads();                   // all warps done reading buffer s
        if (kt + 2 < NTILE) {
            const __half* Kt  = Kg  + (size_t)(kt + 2) * 64 * 64;
            const __half* Vtg = VgT + (size_t)(kt + 2) * 64;
            __half* Kd = Ks + s * 64 * AP;
            __half* Vd = Vs + s * 64 * AP;
#pragma unroll
            for (int i = 0; i < 4; i++) {
                int cidx = tid + i * 128;
                int r = cidx >> 3, kc = cidx & 7;
                cpa16(Kd + r * AP + kc * 8, Kt + (size_t)r * 64 + kc * 8);
                cpa16(Vd + r * AP + kc * 8, Vtg + (size_t)r * L_ + kc * 8);
            }
            CPA_COMMIT();
            CPA_WAIT1();
        } else {
            CPA_WAIT0();
        }
        __syncthreads();                   // kt+1 data visible to all warps
    }

    // Epilogue: write ctx fp16, layout [B,L,H*DH]
#pragma unroll
    for (int hm = 0; hm < 2; hm++) {
        float inv0 = 1.0f / l[hm * 2], inv1 = 1.0f / l[hm * 2 + 1];
        int r0 = q0 + w * 32 + hm * 16 + g;
        int r1 = r0 + 8;
#pragma unroll
        for (int nf = 0; nf < 8; nf++) {
            int col = h * 64 + nf * 8 + 2 * c;
            __half2 u0 = __floats2half2_rn(o[hm][nf][0] * inv0, o[hm][nf][1] * inv0);
            __half2 u1 = __floats2half2_rn(o[hm][nf][2] * inv1, o[hm][nf][3] * inv1);
            *(__half2*)(g_ctx + (size_t)(bb * L_ + r0) * 1024 + col) = u0;
            *(__half2*)(g_ctx + (size_t)(bb * L_ + r1) * 1024 + col) = u1;
        }
    }
}

// ---------------------------------------------------------------------------
// LayerNorm over last dim (1024), one block per token row
// ---------------------------------------------------------------------------
__global__ __launch_bounds__(256) void ln_kernel(
    const float* __restrict__ gamma,
    const float* __restrict__ beta,
    float* __restrict__ out)
{
    const int row = blockIdx.x;
    const float* yr = g_y + (size_t)row * 1024;
    const int tid = threadIdx.x;

    float s = 0.f, sq = 0.f;
#pragma unroll
    for (int i = tid; i < 1024; i += 256) {
        float v = yr[i];
        s += v;
        sq += v * v;
    }
#pragma unroll
    for (int off = 16; off > 0; off >>= 1) {
        s  += __shfl_xor_sync(0xffffffffu, s, off);
        sq += __shfl_xor_sync(0xffffffffu, sq, off);
    }
    __shared__ float ws[8], wq[8];
    __shared__ float mu_s, rstd_s;
    int w = tid >> 5;
    if ((tid & 31) == 0) { ws[w] = s; wq[w] = sq; }
    __syncthreads();
    if (tid == 0) {
        float S = 0.f, Q = 0.f;
#pragma unroll
        for (int i = 0; i < 8; i++) { S += ws[i]; Q += wq[i]; }
        float mu = S * (1.0f / 1024.0f);
        float var = Q * (1.0f / 1024.0f) - mu * mu;
        mu_s = mu;
        rstd_s = rsqrtf(var + 1e-5f);
    }
    __syncthreads();
    float mu = mu_s, rstd = rstd_s;
#pragma unroll
    for (int i = tid; i < 1024; i += 256) {
        out[(size_t)row * 1024 + i] = (yr[i] - mu) * rstd * gamma[i] + beta[i];
    }
}

// ---------------------------------------------------------------------------
extern "C" void kernel_launch(void* const* d_in, const int* in_sizes, int n_in,
                              void* d_out, int out_size)
{
    const float* x      = (const float*)d_in[0];
    // d_in[1] = market_info: softmax-invariant constant, unused
    const float* w_in   = (const float*)d_in[2];
    const float* b_in   = (const float*)d_in[3];
    const float* w_out  = (const float*)d_in[4];
    const float* b_out  = (const float*)d_in[5];
    const float* gamma  = (const float*)d_in[6];
    const float* beta   = (const float*)d_in[7];
    float* out = (float*)d_out;

    // fp32 -> fp16 prep (x, W_in, W_out)
    prep_kernel<<<(NQ_X + NQ_WI + NQ_WO) / 256, 256>>>(x, w_in, w_out);

    // GEMM smem: 2 buffers x (A + B) x 128 x 48 halves = 49152 B -> 3 CTAs/SM
    const int gemm_smem = 4 * 128 * GP * (int)sizeof(__half);
    cudaFuncSetAttribute(qkv_gemm, cudaFuncAttributeMaxDynamicSharedMemorySize, gemm_smem);
    cudaFuncSetAttribute(out_gemm, cudaFuncAttributeMaxDynamicSharedMemorySize, gemm_smem);

    // QKV projection
    qkv_gemm<<<dim3(24, 32), 128, gemm_smem>>>(b_in);

    // Attention: smem = (128 + 2*64 + 2*64) * 80 halves = 61440 B
    const int attn_smem = 384 * AP * (int)sizeof(__half);
    cudaFuncSetAttribute(attn_f16, cudaFuncAttributeMaxDynamicSharedMemorySize,
                         attn_smem);
    attn_f16<<<dim3(L_ / 128, B_ * H_), 128, attn_smem>>>();

    // Output projection + residual
    out_gemm<<<dim3(8, 32), 128, gemm_smem>>>(x, b_out);

    // LayerNorm
    ln_kernel<<<NT, 256>>>(gamma, beta, out);
}